// round 2
// baseline (speedup 1.0000x reference)
#include <cuda_runtime.h>
#include <cstdint>

// HeteroGCNConv: 3-layer weighted GCN.
// Inputs (metadata order): x[N*128] f32, edge_weight[E] f32, W[L*128*128] f32,
//                          b[L*128] f32, src[E] i32, dst[E] i32. Output: [N*128] f32.
//
// Strategy: build dst-CSR once per launch (degree hist + scan + fill), then per
// layer: tiled fp32 GEMM (h @ W[l]) into g_h2, then warp-per-node gather-SpMM
// (reads L2-resident: h2 = 51.2MB < 126MB L2) + bias + ELU. SpMM edge loop is
// unrolled x4 for MLP on the 512B row gathers.

#define D 128
#define NMAX 100000
#define EMAX 1600000
#define CHUNK 1024
#define NCH_MAX ((NMAX + CHUNK - 1) / CHUNK)

__device__ float g_deg_src[NMAX];
__device__ float g_deg_dst[NMAX];
__device__ int   g_cnt[NMAX];
__device__ int   g_fill[NMAX];
__device__ int   g_row_ptr[NMAX + 1];
__device__ int   g_chunk_sum[NCH_MAX + 1];
__device__ int   g_chunk_off[NCH_MAX + 1];
__device__ int2  g_cv[EMAX];                    // (src_node, bitcast(norm_weight))
__device__ float g_hA[(size_t)NMAX * D];        // layer output buffer
__device__ float g_h2[(size_t)NMAX * D];        // post-GEMM buffer

// ---------------- precompute ----------------

__global__ void zero_kernel(int n) {
    int i = blockIdx.x * blockDim.x + threadIdx.x;
    if (i < n) {
        g_deg_src[i] = 0.f;
        g_deg_dst[i] = 0.f;
        g_cnt[i] = 0;
        g_fill[i] = 0;
    }
}

__global__ void deg_kernel(const float* __restrict__ ew,
                           const int* __restrict__ src,
                           const int* __restrict__ dst, int e) {
    int i = blockIdx.x * blockDim.x + threadIdx.x;
    if (i < e) {
        float w = ew[i];
        atomicAdd(&g_deg_src[src[i]], w);
        atomicAdd(&g_deg_dst[dst[i]], w);
        atomicAdd(&g_cnt[dst[i]], 1);
    }
}

// 3-pass exclusive scan of g_cnt -> g_row_ptr
__global__ void scan_a(int n) {
    __shared__ int sh[256];
    int t = threadIdx.x;
    int base = blockIdx.x * CHUNK;
    int s = 0;
    for (int j = t; j < CHUNK; j += 256) {
        int i = base + j;
        s += (i < n) ? g_cnt[i] : 0;
    }
    sh[t] = s;
    __syncthreads();
    for (int off = 128; off > 0; off >>= 1) {
        if (t < off) sh[t] += sh[t + off];
        __syncthreads();
    }
    if (t == 0) g_chunk_sum[blockIdx.x] = sh[0];
}

__global__ void scan_b(int nchunks, int n) {
    __shared__ int sh[NCH_MAX + 1];
    int t = threadIdx.x;
    for (int i = t; i < nchunks; i += blockDim.x) sh[i] = g_chunk_sum[i];
    __syncthreads();
    if (t == 0) {
        int run = 0;
        for (int i = 0; i < nchunks; ++i) {
            int v = sh[i];
            sh[i] = run;
            run += v;
        }
        g_row_ptr[n] = run;   // == E
    }
    __syncthreads();
    for (int i = t; i < nchunks; i += blockDim.x) g_chunk_off[i] = sh[i];
}

__global__ void scan_c(int n) {
    __shared__ int sh[CHUNK];
    int t = threadIdx.x;
    int i = blockIdx.x * CHUNK + t;
    int v = (i < n) ? g_cnt[i] : 0;
    sh[t] = v;
    __syncthreads();
    for (int off = 1; off < CHUNK; off <<= 1) {
        int x = (t >= off) ? sh[t - off] : 0;
        __syncthreads();
        sh[t] += x;
        __syncthreads();
    }
    if (i < n) g_row_ptr[i] = g_chunk_off[blockIdx.x] + sh[t] - v;  // exclusive
}

// fill CSR slots; compute symmetric norm weight inline
__global__ void fill_kernel(const float* __restrict__ ew,
                            const int* __restrict__ src,
                            const int* __restrict__ dst, int e) {
    int i = blockIdx.x * blockDim.x + threadIdx.x;
    if (i < e) {
        int s = src[i], d = dst[i];
        float nw = ew[i] * rsqrtf(g_deg_src[s] * g_deg_dst[d]);
        int pos = g_row_ptr[d] + atomicAdd(&g_fill[d], 1);
        g_cv[pos] = make_int2(s, __float_as_int(nw));
    }
}

// ---------------- per-layer GEMM: C[n,128] = A[n,128] @ W[128,128] ----------------

#define BM 64
#define KT 32

__global__ __launch_bounds__(256) void gemm_kernel(const float* __restrict__ Aext,
                                                   const float* __restrict__ Wl, int n) {
    const float* __restrict__ A = Aext ? Aext : g_hA;
    __shared__ __align__(16) float sA[BM][KT];
    __shared__ __align__(16) float sW[KT][D];

    int t = threadIdx.x;
    int tx = t & 31;       // col group: cols 4*tx..4*tx+3
    int ty = t >> 5;       // warp id: rows ty*8..ty*8+7
    int row0 = blockIdx.x * BM;

    float4 acc[8];
#pragma unroll
    for (int i = 0; i < 8; ++i) acc[i] = make_float4(0.f, 0.f, 0.f, 0.f);

    for (int kt = 0; kt < D; kt += KT) {
        // load A tile (64x32)
#pragma unroll
        for (int idx = t; idx < BM * KT; idx += 256) {
            int r = idx >> 5, c = idx & 31;
            int gr = row0 + r;
            sA[r][c] = (gr < n) ? A[(size_t)gr * D + kt + c] : 0.f;
        }
        // load W tile (32x128)
#pragma unroll
        for (int idx = t; idx < KT * D; idx += 256) {
            int r = idx >> 7, c = idx & 127;
            sW[r][c] = Wl[(size_t)(kt + r) * D + c];
        }
        __syncthreads();
#pragma unroll
        for (int kk = 0; kk < KT; ++kk) {
            float4 w4 = *(const float4*)&sW[kk][tx * 4];
#pragma unroll
            for (int i = 0; i < 8; ++i) {
                float a = sA[ty * 8 + i][kk];   // warp-broadcast LDS
                acc[i].x = fmaf(a, w4.x, acc[i].x);
                acc[i].y = fmaf(a, w4.y, acc[i].y);
                acc[i].z = fmaf(a, w4.z, acc[i].z);
                acc[i].w = fmaf(a, w4.w, acc[i].w);
            }
        }
        __syncthreads();
    }
#pragma unroll
    for (int i = 0; i < 8; ++i) {
        int gr = row0 + ty * 8 + i;
        if (gr < n) *(float4*)&g_h2[(size_t)gr * D + tx * 4] = acc[i];
    }
}

// ---------------- per-layer SpMM + bias + ELU: one warp per dst node ----------------
// Edge loop unrolled x4: four independent 512B row gathers in flight (MLP 4).

__global__ __launch_bounds__(256) void spmm_kernel(const float* __restrict__ bias,
                                                   float* __restrict__ outExt, int n) {
    float* __restrict__ out = outExt ? outExt : g_hA;
    int warp = (blockIdx.x * blockDim.x + threadIdx.x) >> 5;
    int lane = threadIdx.x & 31;
    if (warp >= n) return;

    int p   = g_row_ptr[warp];
    int end = g_row_ptr[warp + 1];
    int c4  = lane * 4;

    float4 acc = make_float4(0.f, 0.f, 0.f, 0.f);

    for (; p + 4 <= end; p += 4) {
        int2 c0 = g_cv[p + 0];
        int2 c1 = g_cv[p + 1];
        int2 c2 = g_cv[p + 2];
        int2 c3 = g_cv[p + 3];
        float4 h0 = *(const float4*)(g_h2 + (size_t)c0.x * D + c4);
        float4 h1 = *(const float4*)(g_h2 + (size_t)c1.x * D + c4);
        float4 h2v = *(const float4*)(g_h2 + (size_t)c2.x * D + c4);
        float4 h3 = *(const float4*)(g_h2 + (size_t)c3.x * D + c4);
        float v0 = __int_as_float(c0.y), v1 = __int_as_float(c1.y);
        float v2 = __int_as_float(c2.y), v3 = __int_as_float(c3.y);
        acc.x = fmaf(v0, h0.x, acc.x); acc.y = fmaf(v0, h0.y, acc.y);
        acc.z = fmaf(v0, h0.z, acc.z); acc.w = fmaf(v0, h0.w, acc.w);
        acc.x = fmaf(v1, h1.x, acc.x); acc.y = fmaf(v1, h1.y, acc.y);
        acc.z = fmaf(v1, h1.z, acc.z); acc.w = fmaf(v1, h1.w, acc.w);
        acc.x = fmaf(v2, h2v.x, acc.x); acc.y = fmaf(v2, h2v.y, acc.y);
        acc.z = fmaf(v2, h2v.z, acc.z); acc.w = fmaf(v2, h2v.w, acc.w);
        acc.x = fmaf(v3, h3.x, acc.x); acc.y = fmaf(v3, h3.y, acc.y);
        acc.z = fmaf(v3, h3.z, acc.z); acc.w = fmaf(v3, h3.w, acc.w);
    }
    for (; p < end; ++p) {
        int2 cv = g_cv[p];
        float v = __int_as_float(cv.y);
        const float4 hv = *(const float4*)(g_h2 + (size_t)cv.x * D + c4);
        acc.x = fmaf(v, hv.x, acc.x);
        acc.y = fmaf(v, hv.y, acc.y);
        acc.z = fmaf(v, hv.z, acc.z);
        acc.w = fmaf(v, hv.w, acc.w);
    }

    float4 bb = *(const float4*)(bias + c4);
    acc.x += bb.x; acc.y += bb.y; acc.z += bb.z; acc.w += bb.w;
    // ELU (alpha=1)
    acc.x = acc.x > 0.f ? acc.x : expm1f(acc.x);
    acc.y = acc.y > 0.f ? acc.y : expm1f(acc.y);
    acc.z = acc.z > 0.f ? acc.z : expm1f(acc.z);
    acc.w = acc.w > 0.f ? acc.w : expm1f(acc.w);
    *(float4*)(out + (size_t)warp * D + c4) = acc;
}

// ---------------- launch ----------------

extern "C" void kernel_launch(void* const* d_in, const int* in_sizes, int n_in,
                              void* d_out, int out_size) {
    const float* x    = (const float*)d_in[0];
    const float* ew   = (const float*)d_in[1];
    const float* Wm   = (const float*)d_in[2];
    const float* bias = (const float*)d_in[3];
    const int*   src  = (const int*)d_in[4];
    const int*   dst  = (const int*)d_in[5];

    int E = in_sizes[1];
    int N = in_sizes[0] / D;
    int L = in_sizes[3] / D;
    int nchunks = (N + CHUNK - 1) / CHUNK;

    zero_kernel<<<(N + 255) / 256, 256>>>(N);
    deg_kernel<<<(E + 255) / 256, 256>>>(ew, src, dst, E);
    scan_a<<<nchunks, 256>>>(N);
    scan_b<<<1, 128>>>(nchunks, N);
    scan_c<<<nchunks, CHUNK>>>(N);
    fill_kernel<<<(E + 255) / 256, 256>>>(ew, src, dst, E);

    const float* curExt = x;   // layer-0 input; nullptr => g_hA afterwards
    for (int l = 0; l < L; ++l) {
        gemm_kernel<<<(N + BM - 1) / BM, 256>>>(curExt, Wm + (size_t)l * D * D, N);
        float* outExt = (l == L - 1) ? (float*)d_out : nullptr;
        spmm_kernel<<<((size_t)N * 32 + 255) / 256, 256>>>(bias + (size_t)l * D, outExt, N);
        curExt = nullptr;
    }
}